// round 1
// baseline (speedup 1.0000x reference)
#include <cuda_runtime.h>

#define NS 100000
#define ND 100000
#define NE 1600000
#define DIN 256
#define NH 4
#define DH 32
#define HD 128
#define NEG 0.2f

// ---- scratch (device globals: no allocations allowed) ----
__device__ float g_fs[(size_t)NS * HD];      // 51.2 MB: transformed src feats
__device__ float g_esrc[NS * NH];
__device__ float g_edst[ND * NH];
__device__ float g_denom[ND * NH];
__device__ float g_vsrc[NH * DIN];           // [h][k] layouts for GEMV
__device__ float g_vdst[NH * DIN];

// ---------------------------------------------------------------------------
// v_src[h][k] = sum_d w_src[k, h*32+d] * attn[h, 32+d]
// v_dst[h][k] = sum_d w_dst[k, h*32+d] * attn[h, d]
// ---------------------------------------------------------------------------
__global__ void k_v(const float* __restrict__ w_src,
                    const float* __restrict__ w_dst,
                    const float* __restrict__ attn) {
    int k = threadIdx.x;  // 0..255
    #pragma unroll
    for (int h = 0; h < NH; h++) {
        float s1 = 0.f, s2 = 0.f;
        #pragma unroll 8
        for (int d = 0; d < DH; d++) {
            s1 += w_src[k * HD + h * DH + d] * attn[h * 2 * DH + DH + d];
            s2 += w_dst[k * HD + h * DH + d] * attn[h * 2 * DH + d];
        }
        g_vsrc[h * DIN + k] = s1;
        g_vdst[h * DIN + k] = s2;
    }
}

// ---------------------------------------------------------------------------
// SGEMM: g_fs = feat_src @ w_src   (M=100000, N=128, K=256)
// BM=128, BN=128, BK=16, 256 threads, 8x8 microtile
// ---------------------------------------------------------------------------
__global__ __launch_bounds__(256, 2)
void k_gemm(const float* __restrict__ A, const float* __restrict__ B, int M) {
    __shared__ float As[16][128];
    __shared__ float Bs[16][128];
    const int bm = blockIdx.x * 128;
    const int tid = threadIdx.x;
    const int tr = tid / 16;       // 0..15
    const int tc = tid % 16;       // 0..15

    float acc[8][8];
    #pragma unroll
    for (int i = 0; i < 8; i++)
        #pragma unroll
        for (int j = 0; j < 8; j++) acc[i][j] = 0.f;

    for (int k0 = 0; k0 < DIN; k0 += 16) {
        #pragma unroll
        for (int i = 0; i < 2; i++) {
            int idx = tid * 2 + i;              // 0..511
            // A tile: 128 rows x 16 cols = 512 float4
            int r  = idx >> 2;
            int c4 = (idx & 3) * 4;
            int grow = bm + r;
            if (grow >= M) grow = M - 1;        // clamp (writes guarded later)
            float4 a4 = *(const float4*)&A[(size_t)grow * DIN + k0 + c4];
            As[c4 + 0][r] = a4.x; As[c4 + 1][r] = a4.y;
            As[c4 + 2][r] = a4.z; As[c4 + 3][r] = a4.w;
            // B tile: 16 rows x 128 cols = 512 float4
            int rb = idx >> 5;
            int cb = (idx & 31) * 4;
            *(float4*)&Bs[rb][cb] = *(const float4*)&B[(size_t)(k0 + rb) * HD + cb];
        }
        __syncthreads();
        #pragma unroll
        for (int k = 0; k < 16; k++) {
            float4 a0 = *(const float4*)&As[k][tr * 8];
            float4 a1 = *(const float4*)&As[k][tr * 8 + 4];
            float4 b0 = *(const float4*)&Bs[k][tc * 8];
            float4 b1 = *(const float4*)&Bs[k][tc * 8 + 4];
            float ar[8] = {a0.x,a0.y,a0.z,a0.w,a1.x,a1.y,a1.z,a1.w};
            float br[8] = {b0.x,b0.y,b0.z,b0.w,b1.x,b1.y,b1.z,b1.w};
            #pragma unroll
            for (int i = 0; i < 8; i++)
                #pragma unroll
                for (int j = 0; j < 8; j++) acc[i][j] += ar[i] * br[j];
        }
        __syncthreads();
    }
    #pragma unroll
    for (int i = 0; i < 8; i++) {
        int grow = bm + tr * 8 + i;
        if (grow < M) {
            #pragma unroll
            for (int j = 0; j < 2; j++) {
                float4 v = make_float4(acc[i][j*4], acc[i][j*4+1], acc[i][j*4+2], acc[i][j*4+3]);
                *(float4*)&g_fs[(size_t)grow * HD + tc * 8 + j * 4] = v;
            }
        }
    }
}

// ---------------------------------------------------------------------------
// GEMV: e[n,h] = feat[n,:] dot v[h,:]  — one warp per node
// WHICH=0: src (g_vsrc -> g_esrc), WHICH=1: dst (g_vdst -> g_edst)
// ---------------------------------------------------------------------------
template <int WHICH>
__global__ __launch_bounds__(256)
void k_e(const float* __restrict__ feat, int n) {
    __shared__ float vs[NH][DIN];
    const float* v = (WHICH == 0) ? g_vsrc : g_vdst;
    float* e = (WHICH == 0) ? g_esrc : g_edst;
    for (int i = threadIdx.x; i < NH * DIN; i += blockDim.x)
        vs[i / DIN][i % DIN] = v[i];
    __syncthreads();

    int warp = (blockIdx.x * blockDim.x + threadIdx.x) >> 5;
    int lane = threadIdx.x & 31;
    int nw = (gridDim.x * blockDim.x) >> 5;
    for (int node = warp; node < n; node += nw) {
        float acc[NH] = {0.f, 0.f, 0.f, 0.f};
        #pragma unroll
        for (int j = 0; j < DIN / 128; j++) {
            int k4 = j * 128 + lane * 4;
            float4 x = *(const float4*)&feat[(size_t)node * DIN + k4];
            #pragma unroll
            for (int h = 0; h < NH; h++) {
                float4 vv = *(const float4*)&vs[h][k4];
                acc[h] += x.x * vv.x + x.y * vv.y + x.z * vv.z + x.w * vv.w;
            }
        }
        #pragma unroll
        for (int h = 0; h < NH; h++) {
            #pragma unroll
            for (int off = 16; off > 0; off >>= 1)
                acc[h] += __shfl_xor_sync(0xffffffffu, acc[h], off);
        }
        if (lane == 0)
            *(float4*)&e[node * NH] = make_float4(acc[0], acc[1], acc[2], acc[3]);
    }
}

// ---------------------------------------------------------------------------
// zero out accumulators: d_out (ND*HD) and g_denom (ND*NH)
// ---------------------------------------------------------------------------
__global__ void k_zero(float* __restrict__ out) {
    const int n_out4 = ND * HD / 4;
    const int n_den4 = ND * NH / 4;
    int i = blockIdx.x * blockDim.x + threadIdx.x;
    float4 z = make_float4(0.f, 0.f, 0.f, 0.f);
    if (i < n_out4) ((float4*)out)[i] = z;
    else if (i < n_out4 + n_den4) ((float4*)g_denom)[i - n_out4] = z;
}

__device__ __forceinline__ void red_add_v4(float* p, float4 v) {
    asm volatile("red.global.add.v4.f32 [%0], {%1,%2,%3,%4};"
                 :: "l"(p), "f"(v.x), "f"(v.y), "f"(v.z), "f"(v.w) : "memory");
}

// ---------------------------------------------------------------------------
// Edge pass: one warp per edge.
//   ex = exp(leakyrelu(e_src[s,h] + e_dst[d,h]))
//   out[d,:] += fs[s,:] * ex[head]     (unnormalized)
//   denom[d,:] += ex
// ---------------------------------------------------------------------------
__global__ __launch_bounds__(256)
void k_edge(const int* __restrict__ src, const int* __restrict__ dst,
            float* __restrict__ out) {
    int warp = (blockIdx.x * blockDim.x + threadIdx.x) >> 5;
    int lane = threadIdx.x & 31;
    int nw = (gridDim.x * blockDim.x) >> 5;
    for (int e = warp; e < NE; e += nw) {
        int s = __ldg(&src[e]);
        int d = __ldg(&dst[e]);
        int h = lane >> 3;  // 8 lanes per head (32 feats / 4 per lane)
        float ev = __ldg(&g_esrc[s * NH + h]) + __ldg(&g_edst[d * NH + h]);
        ev = ev > 0.f ? ev : NEG * ev;
        float ex = __expf(ev);

        float4 f = *(const float4*)&g_fs[(size_t)s * HD + lane * 4];
        red_add_v4(&out[(size_t)d * HD + lane * 4],
                   make_float4(f.x * ex, f.y * ex, f.z * ex, f.w * ex));

        float e0 = __shfl_sync(0xffffffffu, ex, 0);
        float e1 = __shfl_sync(0xffffffffu, ex, 8);
        float e2 = __shfl_sync(0xffffffffu, ex, 16);
        float e3 = __shfl_sync(0xffffffffu, ex, 24);
        if (lane == 0)
            red_add_v4(&g_denom[d * NH], make_float4(e0, e1, e2, e3));
    }
}

// ---------------------------------------------------------------------------
// Finalize: out = relu(out / denom)
// ---------------------------------------------------------------------------
__global__ void k_final(float* __restrict__ out) {
    int i = blockIdx.x * blockDim.x + threadIdx.x;  // float4 index
    if (i >= ND * HD / 4) return;
    int node = i / (HD / 4);
    int c = (i % (HD / 4)) * 4;
    int h = c / DH;
    float den = g_denom[node * NH + h];
    float inv = den > 0.f ? 1.f / den : 0.f;
    float4 v = ((float4*)out)[i];
    v.x = fmaxf(v.x * inv, 0.f);
    v.y = fmaxf(v.y * inv, 0.f);
    v.z = fmaxf(v.z * inv, 0.f);
    v.w = fmaxf(v.w * inv, 0.f);
    ((float4*)out)[i] = v;
}

// ---------------------------------------------------------------------------
extern "C" void kernel_launch(void* const* d_in, const int* in_sizes, int n_in,
                              void* d_out, int out_size) {
    const float* feat_src = (const float*)d_in[0];
    const float* feat_dst = (const float*)d_in[1];
    const float* w_src    = (const float*)d_in[2];
    const float* w_dst    = (const float*)d_in[3];
    const float* attn     = (const float*)d_in[4];
    const int*   src_idx  = (const int*)d_in[5];
    const int*   dst_idx  = (const int*)d_in[6];
    float* out = (float*)d_out;

    k_v<<<1, 256>>>(w_src, w_dst, attn);
    k_gemm<<<(NS + 127) / 128, 256>>>(feat_src, w_src, NS);
    k_e<0><<<(NS + 7) / 8, 256>>>(feat_src, NS);
    k_e<1><<<(ND + 7) / 8, 256>>>(feat_dst, ND);
    {
        int total4 = (ND * HD + ND * NH) / 4;
        k_zero<<<(total4 + 255) / 256, 256>>>(out);
    }
    k_edge<<<8192, 256>>>(src_idx, dst_idx, out);
    k_final<<<(ND * HD / 4 + 255) / 256, 256>>>(out);
}

// round 4
// speedup vs baseline: 1.0123x; 1.0123x over previous
#include <cuda_runtime.h>

#define NS 100000
#define ND 100000
#define NE 1600000
#define DIN 256
#define NH 4
#define DH 32
#define HD 128
#define NEG 0.2f

// ---- scratch (device globals: no allocations allowed) ----
__device__ float g_fs[(size_t)NS * HD];      // 51.2 MB: transformed src feats
__device__ float g_esrc[NS * NH];
__device__ float g_edst[ND * NH];
__device__ float g_denom[ND * NH];
__device__ float g_vdst[NH * DIN];           // [h][k] layout for dst GEMV

// ---------------------------------------------------------------------------
// v_dst[h][k] = sum_d w_dst[k, h*32+d] * attn[h, d]
// ---------------------------------------------------------------------------
__global__ void k_v(const float* __restrict__ w_dst,
                    const float* __restrict__ attn) {
    int k = threadIdx.x;  // 0..255
    #pragma unroll
    for (int h = 0; h < NH; h++) {
        float s2 = 0.f;
        #pragma unroll 8
        for (int d = 0; d < DH; d++)
            s2 += w_dst[k * HD + h * DH + d] * attn[h * 2 * DH + d];
        g_vdst[h * DIN + k] = s2;
    }
}

// ---------------------------------------------------------------------------
// zero: d_out (ND*HD), g_denom (ND*NH), g_esrc (NS*NH)
// ---------------------------------------------------------------------------
__global__ void k_zero(float* __restrict__ out) {
    const int n_out4 = ND * HD / 4;
    const int n_den4 = ND * NH / 4;
    const int n_es4  = NS * NH / 4;
    int i = blockIdx.x * blockDim.x + threadIdx.x;
    float4 z = make_float4(0.f, 0.f, 0.f, 0.f);
    if (i < n_out4) ((float4*)out)[i] = z;
    else if (i < n_out4 + n_den4) ((float4*)g_denom)[i - n_out4] = z;
    else if (i < n_out4 + n_den4 + n_es4) ((float4*)g_esrc)[i - n_out4 - n_den4] = z;
}

// ---------------------------------------------------------------------------
// TF32 helpers
// ---------------------------------------------------------------------------
__device__ __forceinline__ unsigned f2tf32(float f) {
    unsigned u;
    asm("cvt.rna.tf32.f32 %0, %1;" : "=r"(u) : "f"(f));
    return u;
}
__device__ __forceinline__ void mma_tf32(float* c, const unsigned* a, const unsigned* b) {
    asm volatile(
        "mma.sync.aligned.m16n8k8.row.col.f32.tf32.tf32.f32 "
        "{%0,%1,%2,%3}, {%4,%5,%6,%7}, {%8,%9}, {%0,%1,%2,%3};\n"
        : "+f"(c[0]), "+f"(c[1]), "+f"(c[2]), "+f"(c[3])
        : "r"(a[0]), "r"(a[1]), "r"(a[2]), "r"(a[3]), "r"(b[0]), "r"(b[1]));
}
__device__ __forceinline__ void red_add_v2(float* p, float x, float y) {
    asm volatile("red.global.add.v2.f32 [%0], {%1,%2};"
                 :: "l"(p), "f"(x), "f"(y) : "memory");
}
__device__ __forceinline__ void red_add_v4(float* p, float4 v) {
    asm volatile("red.global.add.v4.f32 [%0], {%1,%2,%3,%4};"
                 :: "l"(p), "f"(v.x), "f"(v.y), "f"(v.z), "f"(v.w) : "memory");
}

// ---------------------------------------------------------------------------
// 3xTF32 GEMM: g_fs = feat_src @ w_src  (M=100000, N=128, K=256)
// BM=128, BN=128, BK=16; 8 warps (4M x 2N), warp tile 32x64.
// Error-compensated: Ah*Bh + Al*Bh + Ah*Bl  (rel err ~1e-7).
// Epilogue fuses e_src[n,h] = sum_d fs[n,h*32+d]*attn[h,32+d] via red.add.
// ---------------------------------------------------------------------------
#define PA 136
#define PB 136

__global__ __launch_bounds__(256, 1)
void k_gemm(const float* __restrict__ A, const float* __restrict__ B,
            const float* __restrict__ attn, int M) {
    __shared__ unsigned Ah[16 * PA], Al[16 * PA];
    __shared__ unsigned Bh[16 * PB], Bl[16 * PB];
    __shared__ float at[HD];

    const int tid = threadIdx.x;
    const int bm = blockIdx.x * 128;
    const int wid = tid >> 5;
    const int lane = tid & 31;
    const int warpM = wid >> 1;          // 0..3
    const int warpN = wid & 1;           // 0..1
    const int g = lane >> 2;             // 0..7
    const int t = lane & 3;              // 0..3

    if (tid < HD)
        at[tid] = attn[(tid >> 5) * (2 * DH) + DH + (tid & 31)];

    float acc[2][8][4];
    #pragma unroll
    for (int m = 0; m < 2; m++)
        #pragma unroll
        for (int n = 0; n < 8; n++)
            #pragma unroll
            for (int q = 0; q < 4; q++) acc[m][n][q] = 0.f;

    for (int k0 = 0; k0 < DIN; k0 += 16) {
        // load + split A tile (128x16) transposed into Ah/Al [k][m]
        #pragma unroll
        for (int i = 0; i < 2; i++) {
            int idx = tid * 2 + i;          // 0..511
            int r = idx >> 2;
            int c4 = (idx & 3) * 4;
            int grow = bm + r;
            if (grow >= M) grow = M - 1;
            float4 a4 = *(const float4*)&A[(size_t)grow * DIN + k0 + c4];
            float av[4] = {a4.x, a4.y, a4.z, a4.w};
            #pragma unroll
            for (int q = 0; q < 4; q++) {
                unsigned hi = f2tf32(av[q]);
                float lo_f = av[q] - __uint_as_float(hi);
                Ah[(c4 + q) * PA + r] = hi;
                Al[(c4 + q) * PA + r] = f2tf32(lo_f);
            }
            // B tile (16x128) natural layout
            int rb = idx >> 5;
            int cb = (idx & 31) * 4;
            float4 b4 = *(const float4*)&B[(size_t)(k0 + rb) * HD + cb];
            float bv[4] = {b4.x, b4.y, b4.z, b4.w};
            #pragma unroll
            for (int q = 0; q < 4; q++) {
                unsigned hi = f2tf32(bv[q]);
                float lo_f = bv[q] - __uint_as_float(hi);
                Bh[rb * PB + cb + q] = hi;
                Bl[rb * PB + cb + q] = f2tf32(lo_f);
            }
        }
        __syncthreads();

        #pragma unroll
        for (int s = 0; s < 2; s++) {
            const int kk = s * 8;
            unsigned ah[2][4], al[2][4];
            #pragma unroll
            for (int m = 0; m < 2; m++) {
                int row = warpM * 32 + m * 16 + g;
                ah[m][0] = Ah[(kk + t) * PA + row];
                ah[m][1] = Ah[(kk + t) * PA + row + 8];
                ah[m][2] = Ah[(kk + t + 4) * PA + row];
                ah[m][3] = Ah[(kk + t + 4) * PA + row + 8];
                al[m][0] = Al[(kk + t) * PA + row];
                al[m][1] = Al[(kk + t) * PA + row + 8];
                al[m][2] = Al[(kk + t + 4) * PA + row];
                al[m][3] = Al[(kk + t + 4) * PA + row + 8];
            }
            #pragma unroll
            for (int n = 0; n < 8; n++) {
                int col = warpN * 64 + n * 8 + g;
                unsigned bh[2], bl[2];
                bh[0] = Bh[(kk + t) * PB + col];
                bh[1] = Bh[(kk + t + 4) * PB + col];
                bl[0] = Bl[(kk + t) * PB + col];
                bl[1] = Bl[(kk + t + 4) * PB + col];
                #pragma unroll
                for (int m = 0; m < 2; m++) {
                    mma_tf32(acc[m][n], ah[m], bh);
                    mma_tf32(acc[m][n], al[m], bh);
                    mma_tf32(acc[m][n], ah[m], bl);
                }
            }
        }
        __syncthreads();
    }

    // epilogue: store fs + fused e_src reduction
    const int hA = 2 * warpN;
    #pragma unroll
    for (int m = 0; m < 2; m++) {
        int row0 = bm + warpM * 32 + m * 16 + g;
        int row1 = row0 + 8;
        float s0a = 0.f, s0b = 0.f, s1a = 0.f, s1b = 0.f;
        #pragma unroll
        for (int n = 0; n < 8; n++) {
            int col = warpN * 64 + n * 8 + 2 * t;
            float a0 = at[col], a1 = at[col + 1];
            if (n < 4) { s0a += acc[m][n][0] * a0 + acc[m][n][1] * a1;
                         s1a += acc[m][n][2] * a0 + acc[m][n][3] * a1; }
            else       { s0b += acc[m][n][0] * a0 + acc[m][n][1] * a1;
                         s1b += acc[m][n][2] * a0 + acc[m][n][3] * a1; }
            if (row0 < M)
                *(float2*)&g_fs[(size_t)row0 * HD + col] = make_float2(acc[m][n][0], acc[m][n][1]);
            if (row1 < M)
                *(float2*)&g_fs[(size_t)row1 * HD + col] = make_float2(acc[m][n][2], acc[m][n][3]);
        }
        if (row0 < M) red_add_v2(&g_esrc[row0 * NH + hA], s0a, s0b);
        if (row1 < M) red_add_v2(&g_esrc[row1 * NH + hA], s1a, s1b);
    }
}

// ---------------------------------------------------------------------------
// GEMV: e_dst[n,h] = feat_dst[n,:] dot v_dst[h,:]  — one warp per node
// ---------------------------------------------------------------------------
__global__ __launch_bounds__(256)
void k_e(const float* __restrict__ feat, int n) {
    __shared__ float vs[NH][DIN];
    for (int i = threadIdx.x; i < NH * DIN; i += blockDim.x)
        vs[i / DIN][i % DIN] = g_vdst[i];
    __syncthreads();

    int warp = (blockIdx.x * blockDim.x + threadIdx.x) >> 5;
    int lane = threadIdx.x & 31;
    int nw = (gridDim.x * blockDim.x) >> 5;
    for (int node = warp; node < n; node += nw) {
        float acc[NH] = {0.f, 0.f, 0.f, 0.f};
        #pragma unroll
        for (int j = 0; j < DIN / 128; j++) {
            int k4 = j * 128 + lane * 4;
            float4 x = *(const float4*)&feat[(size_t)node * DIN + k4];
            #pragma unroll
            for (int h = 0; h < NH; h++) {
                float4 vv = *(const float4*)&vs[h][k4];
                acc[h] += x.x * vv.x + x.y * vv.y + x.z * vv.z + x.w * vv.w;
            }
        }
        #pragma unroll
        for (int h = 0; h < NH; h++) {
            #pragma unroll
            for (int off = 16; off > 0; off >>= 1)
                acc[h] += __shfl_xor_sync(0xffffffffu, acc[h], off);
        }
        if (lane == 0)
            *(float4*)&g_edst[node * NH] = make_float4(acc[0], acc[1], acc[2], acc[3]);
    }
}

// ---------------------------------------------------------------------------
// Edge pass: one warp per edge.
//   ex = exp(leakyrelu(e_src[s,h] + e_dst[d,h]))
//   out[d,:] += fs[s,:] * ex[head]     (unnormalized)
//   denom[d,:] += ex
// ---------------------------------------------------------------------------
__global__ __launch_bounds__(256)
void k_edge(const int* __restrict__ src, const int* __restrict__ dst,
            float* __restrict__ out) {
    int warp = (blockIdx.x * blockDim.x + threadIdx.x) >> 5;
    int lane = threadIdx.x & 31;
    int nw = (gridDim.x * blockDim.x) >> 5;
    for (int e = warp; e < NE; e += nw) {
        int s = __ldg(&src[e]);
        int d = __ldg(&dst[e]);
        int h = lane >> 3;  // 8 lanes per head (32 feats / 4 per lane)
        float ev = __ldg(&g_esrc[s * NH + h]) + __ldg(&g_edst[d * NH + h]);
        ev = ev > 0.f ? ev : NEG * ev;
        float ex = __expf(ev);

        float4 f = *(const float4*)&g_fs[(size_t)s * HD + lane * 4];
        red_add_v4(&out[(size_t)d * HD + lane * 4],
                   make_float4(f.x * ex, f.y * ex, f.z * ex, f.w * ex));

        float e0 = __shfl_sync(0xffffffffu, ex, 0);
        float e1 = __shfl_sync(0xffffffffu, ex, 8);
        float e2 = __shfl_sync(0xffffffffu, ex, 16);
        float e3 = __shfl_sync(0xffffffffu, ex, 24);
        if (lane == 0)
            red_add_v4(&g_denom[d * NH], make_float4(e0, e1, e2, e3));
    }
}

// ---------------------------------------------------------------------------
// Finalize: out = relu(out / denom)
// ---------------------------------------------------------------------------
__global__ void k_final(float* __restrict__ out) {
    int i = blockIdx.x * blockDim.x + threadIdx.x;  // float4 index
    if (i >= ND * HD / 4) return;
    int node = i / (HD / 4);
    int c = (i % (HD / 4)) * 4;
    int h = c / DH;
    float den = g_denom[node * NH + h];
    float inv = den > 0.f ? 1.f / den : 0.f;
    float4 v = ((float4*)out)[i];
    v.x = fmaxf(v.x * inv, 0.f);
    v.y = fmaxf(v.y * inv, 0.f);
    v.z = fmaxf(v.z * inv, 0.f);
    v.w = fmaxf(v.w * inv, 0.f);
    ((float4*)out)[i] = v;
}

// ---------------------------------------------------------------------------
extern "C" void kernel_launch(void* const* d_in, const int* in_sizes, int n_in,
                              void* d_out, int out_size) {
    const float* feat_src = (const float*)d_in[0];
    const float* feat_dst = (const float*)d_in[1];
    const float* w_src    = (const float*)d_in[2];
    const float* w_dst    = (const float*)d_in[3];
    const float* attn     = (const float*)d_in[4];
    const int*   src_idx  = (const int*)d_in[5];
    const int*   dst_idx  = (const int*)d_in[6];
    float* out = (float*)d_out;

    k_v<<<1, 256>>>(w_dst, attn);
    {
        int total4 = (ND * HD + ND * NH + NS * NH) / 4;
        k_zero<<<(total4 + 255) / 256, 256>>>(out);
    }
    k_gemm<<<(NS + 127) / 128, 256>>>(feat_src, w_src, attn, NS);
    k_e<<<(ND + 7) / 8, 256>>>(feat_dst, ND);
    k_edge<<<8192, 256>>>(src_idx, dst_idx, out);
    k_final<<<(ND * HD / 4 + 255) / 256, 256>>>(out);
}